// round 14
// baseline (speedup 1.0000x reference)
#include <cuda_runtime.h>
#include <cuda_fp16.h>
#include <cstdint>

// -------------------- problem constants --------------------
#define B_DIM    4
#define N_NODES  20000
#define K_NB     16
#define IN_DIM_  256
#define C_HID    64
#define H_HEADS  4
#define M_ROWS   (B_DIM * N_NODES)     // 80000
#define OUT_CH   256                   // H*C_H
#define NTILE_M  625                   // 80000 / 128
#define NROW2    74                    // 296 CTAs = 2/SM * 148

// -------------------- scratch (static, no allocs) --------------------
__device__ __half g_h16[(size_t)M_ROWS * OUT_CH];    // 41 MB
__device__ __half g_W16[OUT_CH][IN_DIM_];
__device__ float  g_uv[8][IN_DIM_];
__device__ float  g_ssrc[M_ROWS * H_HEADS];
__device__ float  g_sdst[M_ROWS * H_HEADS];

// -------------------- asm helpers (sm_100-safe, proven) ----------
__device__ __forceinline__ uint32_t smem_u32(const void* p) {
    uint32_t a;
    asm("{ .reg .u64 t; cvta.to.shared.u64 t, %1; cvt.u32.u64 %0, t; }" : "=r"(a) : "l"(p));
    return a;
}
#define CP_ASYNC16(saddr, gptr) \
    asm volatile("{ .reg .u64 g; cvta.to.global.u64 g, %1; cp.async.cg.shared.global [%0], [g], 16; }" \
        :: "r"(saddr), "l"(gptr) : "memory")
#define CP_COMMIT() asm volatile("cp.async.commit_group;" ::: "memory")
#define CP_WAIT0()  asm volatile("cp.async.wait_group 0;" ::: "memory")
#define LDMX4(r0, r1, r2, r3, addr) \
    asm volatile("ldmatrix.sync.aligned.m8n8.x4.shared.b16 {%0,%1,%2,%3}, [%4];" \
        : "=r"(r0), "=r"(r1), "=r"(r2), "=r"(r3) : "r"(addr))
#define MMA16816(d, a, b) \
    asm volatile("mma.sync.aligned.m16n8k16.row.col.f32.f16.f16.f32 " \
        "{%0,%1,%2,%3},{%4,%5,%6,%7},{%8,%9},{%0,%1,%2,%3};" \
        : "+f"((d)[0]), "+f"((d)[1]), "+f"((d)[2]), "+f"((d)[3]) \
        : "r"((a)[0]), "r"((a)[1]), "r"((a)[2]), "r"((a)[3]), "r"((b)[0]), "r"((b)[1]))

// ---------------------------------------------------------------------------
// Kernel A: merged prep (W->fp16, uv fold)
// ---------------------------------------------------------------------------
__global__ void prep_kernel(const float* __restrict__ W, const float* __restrict__ attn) {
    int bid = blockIdx.x;
    int k = threadIdx.x;
    if (bid < OUT_CH) {
        g_W16[bid][k] = __float2half_rn(W[bid * IN_DIM_ + k]);
    } else {
        int t = bid - OUT_CH;
        int h = t & 3, side = t >> 2;
        float acc = 0.f;
#pragma unroll 8
        for (int c = 0; c < C_HID; c++)
            acc += W[(h * C_HID + c) * IN_DIM_ + k] * __ldg(&attn[h * 128 + side * C_HID + c]);
        g_uv[t][k] = acc;
    }
}

// ---------------------------------------------------------------------------
// Kernel D: FUSED persistent GEMM + x-convert + scores.
// grid (4, 74) = 296 CTAs (2/SM). Per tile:
//   phase 1: warp-per-row convert x fp32 -> fp16 into swizzled A smem
//            (full K, 8 kc-sections of 8KB) + fused score dots
//   phase 2: 8 kc MMA steps from smem; epilogue -> g_h16
// B slice (32KB) loaded once per CTA via cp.async.
// ---------------------------------------------------------------------------
#define GSM_B_BYTES   32768
#define GSM_A_BYTES   65536
#define GSM_TOTAL     (GSM_B_BYTES + GSM_A_BYTES)   // 98304

__global__ __launch_bounds__(256, 2)
void gemm_fused_kernel(const float* __restrict__ x) {
    extern __shared__ char smem[];
    const uint32_t Bq = smem_u32(smem);
    const uint32_t Aq = Bq + GSM_B_BYTES;

    const int tid = threadIdx.x, lane = tid & 31, wid = tid >> 5;
    const int nBase = blockIdx.x * 64;
    const int by = blockIdx.y;
    const int wm = wid >> 1;
    const int wn = wid & 1;

    const int ntiles = (NTILE_M - 1 - by) / NROW2 + 1;

    // ---- B: load W n-slice once (2048 x 16B chunks)
    {
#pragma unroll
        for (int i = 0; i < 8; i++) {
            int cid = i * 256 + tid;
            int n = cid >> 5;
            int c = cid & 31;
            const __half* g = &g_W16[nBase + n][c * 8];
            uint32_t s = Bq + n * 512 + ((c ^ (n & 7)) << 4);
            CP_ASYNC16(s, g);
        }
        CP_COMMIT();
    }

    // ---- hoisted ldmatrix addresses (stage offset = kc*8192 at use)
    uint32_t aAddr[2][2];
#pragma unroll
    for (int mi = 0; mi < 2; mi++) {
        int row = wm * 32 + mi * 16 + (lane & 15);
#pragma unroll
        for (int s = 0; s < 2; s++) {
            int c = s * 2 + (lane >> 4);
            aAddr[mi][s] = Aq + row * 64 + ((c ^ ((row >> 1) & 3)) << 4);
        }
    }
    uint32_t bAddr[2][2], bx[2];
#pragma unroll
    for (int bi = 0; bi < 2; bi++) {
        int nrow = wn * 32 + bi * 16 + (lane & 15);
        bx[bi] = (nrow & 4) << 4;
#pragma unroll
        for (int s = 0; s < 2; s++) {
            int t = s * 2 + (lane >> 4);
            bAddr[bi][s] = Bq + nrow * 512 + ((t ^ (nrow & 3)) << 4);
        }
    }

    // conversion-phase constants: lane owns dims [8*lane, 8*lane+8)
    // -> kc section = lane>>2, ac = lane&3
    const uint32_t convBase = Aq + ((uint32_t)(lane >> 2) << 13);
    const int ac = lane & 3;

    float acc[2][4][4];
#pragma unroll
    for (int mi = 0; mi < 2; mi++)
#pragma unroll
        for (int ni = 0; ni < 4; ni++)
#pragma unroll
            for (int q = 0; q < 4; q++) acc[mi][ni][q] = 0.f;

    for (int t = 0; t < ntiles; t++) {
        const int mBase = (by + t * NROW2) * 128;

        // ================= phase 1: convert + scores =================
        {
            // per-lane uv slice (reloaded per tile; L1-hot after tile 0)
            float uvr[8][8];
#pragma unroll
            for (int u = 0; u < 8; u++) {
                float4 a = __ldg((const float4*)&g_uv[u][lane * 8]);
                float4 bq = __ldg((const float4*)&g_uv[u][lane * 8 + 4]);
                uvr[u][0] = a.x;  uvr[u][1] = a.y;  uvr[u][2] = a.z;  uvr[u][3] = a.w;
                uvr[u][4] = bq.x; uvr[u][5] = bq.y; uvr[u][6] = bq.z; uvr[u][7] = bq.w;
            }
#pragma unroll 2
            for (int r = 0; r < 16; r++) {
                const int lrow = wid * 16 + r;
                const int row = mBase + lrow;
                const float4* xp = (const float4*)(x + (size_t)row * IN_DIM_) + lane * 2;
                float4 v0 = xp[0], v1 = xp[1];
                float xv[8] = {v0.x, v0.y, v0.z, v0.w, v1.x, v1.y, v1.z, v1.w};

                // fp16 convert -> swizzled A smem (16B per lane-row)
                __half2 hh[4];
                hh[0] = __floats2half2_rn(xv[0], xv[1]);
                hh[1] = __floats2half2_rn(xv[2], xv[3]);
                hh[2] = __floats2half2_rn(xv[4], xv[5]);
                hh[3] = __floats2half2_rn(xv[6], xv[7]);
                uint32_t saddr = convBase + lrow * 64 + ((ac ^ ((lrow >> 1) & 3)) << 4);
                *(uint4*)(smem + (saddr - smem_u32(smem))) = *(uint4*)hh;

                // score dots
                float sacc[8];
#pragma unroll
                for (int u = 0; u < 8; u++) {
                    float s = 0.f;
#pragma unroll
                    for (int i = 0; i < 8; i++) s = fmaf(xv[i], uvr[u][i], s);
                    sacc[u] = s;
                }
#pragma unroll
                for (int u = 0; u < 8; u++) {
#pragma unroll
                    for (int off = 16; off > 0; off >>= 1)
                        sacc[u] += __shfl_xor_sync(0xffffffffu, sacc[u], off);
                }
                if (lane == 0) {
                    *(float4*)&g_ssrc[row * H_HEADS] = make_float4(sacc[0], sacc[1], sacc[2], sacc[3]);
                    *(float4*)&g_sdst[row * H_HEADS] = make_float4(sacc[4], sacc[5], sacc[6], sacc[7]);
                }
            }
        }
        if (t == 0) CP_WAIT0();      // B arrival (once)
        __syncthreads();

        // ================= phase 2: MMA =================
#pragma unroll
        for (int kc = 0; kc < 8; kc++) {
            const uint32_t stOff = (uint32_t)kc << 13;
            const uint32_t kcb = kc << 6;
#pragma unroll
            for (int s = 0; s < 2; s++) {
                uint32_t a[2][4];
#pragma unroll
                for (int mi = 0; mi < 2; mi++)
                    LDMX4(a[mi][0], a[mi][1], a[mi][2], a[mi][3], aAddr[mi][s] + stOff);
                uint32_t b[4][2];
#pragma unroll
                for (int bi = 0; bi < 2; bi++) {
                    uint32_t r0, r1, r2, r3;
                    LDMX4(r0, r1, r2, r3, bAddr[bi][s] + (kcb ^ bx[bi]));
                    b[bi * 2 + 0][0] = r0; b[bi * 2 + 0][1] = r2;
                    b[bi * 2 + 1][0] = r1; b[bi * 2 + 1][1] = r3;
                }
#pragma unroll
                for (int mi = 0; mi < 2; mi++)
#pragma unroll
                    for (int ni = 0; ni < 4; ni++)
                        MMA16816(acc[mi][ni], a[mi], b[ni]);
            }
        }

        // ---- epilogue: fp32 acc -> fp16 h ; reset acc
#pragma unroll
        for (int mi = 0; mi < 2; mi++)
#pragma unroll
            for (int ni = 0; ni < 4; ni++) {
                int row0 = mBase + wm * 32 + mi * 16 + (lane >> 2);
                int col  = nBase + wn * 32 + ni * 8 + (lane & 3) * 2;
                __half2 v0 = __floats2half2_rn(acc[mi][ni][0], acc[mi][ni][1]);
                __half2 v1 = __floats2half2_rn(acc[mi][ni][2], acc[mi][ni][3]);
                *(__half2*)&g_h16[(size_t)row0 * OUT_CH + col] = v0;
                *(__half2*)&g_h16[(size_t)(row0 + 8) * OUT_CH + col] = v1;
#pragma unroll
                for (int qq = 0; qq < 4; qq++) acc[mi][ni][qq] = 0.f;
            }
        __syncthreads();   // A smem reused by next tile's conversion
    }
}

// ---------------------------------------------------------------------------
// Kernel E: softmax + aggregation (R12 HFMA2 version — at L2 roofline)
// ---------------------------------------------------------------------------
__global__ __launch_bounds__(256)
void agg_kernel(const int* __restrict__ nidx, float* __restrict__ out) {
    __shared__ float salpha[8][H_HEADS][K_NB];
    int gw   = (blockIdx.x * blockDim.x + threadIdx.x) >> 5;
    int lane = threadIdx.x & 31;
    int wid  = (threadIdx.x >> 5);
    if (gw >= M_ROWS) return;

    const int b = gw / N_NODES;
    const int k = lane & 15;
    const int j = __ldg(&nidx[gw * K_NB + k]);
    const int jr = b * N_NODES + j;
    const float scale = 0.125f;

    float4 ssv = *(const float4*)&g_ssrc[gw * H_HEADS];
    float4 sdv = *(const float4*)&g_sdst[jr * H_HEADS];
    float e[H_HEADS] = {(ssv.x + sdv.x) * scale, (ssv.y + sdv.y) * scale,
                        (ssv.z + sdv.z) * scale, (ssv.w + sdv.w) * scale};
    float alpha[H_HEADS];
#pragma unroll
    for (int hh = 0; hh < H_HEADS; hh++) {
        float m = e[hh];
#pragma unroll
        for (int off = 8; off > 0; off >>= 1)
            m = fmaxf(m, __shfl_xor_sync(0xffffffffu, m, off));
        float ex = __expf(e[hh] - m);
        float s = ex;
#pragma unroll
        for (int off = 8; off > 0; off >>= 1)
            s += __shfl_xor_sync(0xffffffffu, s, off);
        alpha[hh] = ex / s;
    }
    if (lane < 16) {
#pragma unroll
        for (int hh = 0; hh < H_HEADS; hh++)
            salpha[wid][hh][lane] = alpha[hh];
    }
    __syncwarp();

    const int myhead = lane >> 3;
    __half2 wh[16];
    {
        float wtmp[16];
#pragma unroll
        for (int qq = 0; qq < 4; qq++)
            *(float4*)&wtmp[qq * 4] = *(const float4*)&salpha[wid][myhead][qq * 4];
#pragma unroll
        for (int kk = 0; kk < 16; kk++) wh[kk] = __float2half2_rn(wtmp[kk]);
    }
    int jarr[16];
    {
        const int4* np = (const int4*)&nidx[gw * K_NB];
#pragma unroll
        for (int qq = 0; qq < 4; qq++)
            *(int4*)&jarr[qq * 4] = __ldg(&np[qq]);
    }

    const __half* hbase = g_h16 + ((size_t)b * N_NODES) * OUT_CH + lane * 8;

    __half2 accA[4], accB[4];
#pragma unroll
    for (int i = 0; i < 4; i++) {
        accA[i] = __float2half2_rn(0.f);
        accB[i] = __float2half2_rn(0.f);
    }

#pragma unroll
    for (int kk = 0; kk < 8; kk++) {
        const uint4 v = *(const uint4*)(hbase + (size_t)jarr[kk] * OUT_CH);
        const __half2* hv = (const __half2*)&v;
#pragma unroll
        for (int qq = 0; qq < 4; qq++)
            accA[qq] = __hfma2(wh[kk], hv[qq], accA[qq]);
    }
#pragma unroll
    for (int kk = 8; kk < 16; kk++) {
        const uint4 v = *(const uint4*)(hbase + (size_t)jarr[kk] * OUT_CH);
        const __half2* hv = (const __half2*)&v;
#pragma unroll
        for (int qq = 0; qq < 4; qq++)
            accB[qq] = __hfma2(wh[kk], hv[qq], accB[qq]);
    }

    float acc[8];
#pragma unroll
    for (int qq = 0; qq < 4; qq++) {
        float2 fa = __half22float2(accA[qq]);
        float2 fb = __half22float2(accB[qq]);
        acc[2 * qq + 0] = fa.x + fb.x;
        acc[2 * qq + 1] = fa.y + fb.y;
    }

#pragma unroll
    for (int i = 0; i < 8; i++) {
        acc[i] += __shfl_xor_sync(0xffffffffu, acc[i], 8);
        acc[i] += __shfl_xor_sync(0xffffffffu, acc[i], 16);
    }

    if (lane < 8) {
        float4 o0 = make_float4(acc[0] * 0.25f, acc[1] * 0.25f, acc[2] * 0.25f, acc[3] * 0.25f);
        float4 o1 = make_float4(acc[4] * 0.25f, acc[5] * 0.25f, acc[6] * 0.25f, acc[7] * 0.25f);
        float* op = out + (size_t)gw * C_HID + lane * 8;
        *(float4*)op = o0;
        *(float4*)(op + 4) = o1;
    }
}

// ---------------------------------------------------------------------------
extern "C" void kernel_launch(void* const* d_in, const int* in_sizes, int n_in,
                              void* d_out, int out_size) {
    const float* x    = (const float*)d_in[0];
    const int*   nidx = (const int*)d_in[1];
    const float* W    = (const float*)d_in[2];
    const float* attn = (const float*)d_in[3];
    float* out = (float*)d_out;

    cudaFuncSetAttribute(gemm_fused_kernel, cudaFuncAttributeMaxDynamicSharedMemorySize, GSM_TOTAL);

    prep_kernel<<<OUT_CH + 8, 256>>>(W, attn);
    gemm_fused_kernel<<<dim3(4, NROW2), 256, GSM_TOTAL>>>(x);
    agg_kernel<<<M_ROWS / 8, 256>>>(nidx, out);
}

// round 15
// speedup vs baseline: 1.3524x; 1.3524x over previous
#include <cuda_runtime.h>
#include <cuda_fp16.h>
#include <cstdint>

// -------------------- problem constants --------------------
#define B_DIM    4
#define N_NODES  20000
#define K_NB     16
#define IN_DIM_  256
#define C_HID    64
#define H_HEADS  4
#define M_ROWS   (B_DIM * N_NODES)     // 80000
#define OUT_CH   256                   // H*C_H
#define NTILE_M  625
#define NROW     111                   // 444 CTAs = 3/SM

// -------------------- scratch (static, no allocs) --------------------
__device__ __half g_h16[(size_t)M_ROWS * OUT_CH];
__device__ __half g_x16[(size_t)M_ROWS * IN_DIM_];
__device__ __half g_W16[OUT_CH][IN_DIM_];
__device__ float  g_uv[8][IN_DIM_];
__device__ float  g_ssrc[M_ROWS * H_HEADS];
__device__ float  g_sdst[M_ROWS * H_HEADS];

// -------------------- asm helpers (sm_100-safe, proven) ----------
__device__ __forceinline__ uint32_t smem_u32(const void* p) {
    uint32_t a;
    asm("{ .reg .u64 t; cvta.to.shared.u64 t, %1; cvt.u32.u64 %0, t; }" : "=r"(a) : "l"(p));
    return a;
}
#define CP_ASYNC16(saddr, gptr) \
    asm volatile("{ .reg .u64 g; cvta.to.global.u64 g, %1; cp.async.cg.shared.global [%0], [g], 16; }" \
        :: "r"(saddr), "l"(gptr) : "memory")
#define CP_COMMIT() asm volatile("cp.async.commit_group;" ::: "memory")
#define CP_WAIT1()  asm volatile("cp.async.wait_group 1;" ::: "memory")
#define LDMX4(r0, r1, r2, r3, addr) \
    asm volatile("ldmatrix.sync.aligned.m8n8.x4.shared.b16 {%0,%1,%2,%3}, [%4];" \
        : "=r"(r0), "=r"(r1), "=r"(r2), "=r"(r3) : "r"(addr))
#define MMA16816(d, a, b) \
    asm volatile("mma.sync.aligned.m16n8k16.row.col.f32.f16.f16.f32 " \
        "{%0,%1,%2,%3},{%4,%5,%6,%7},{%8,%9},{%0,%1,%2,%3};" \
        : "+f"((d)[0]), "+f"((d)[1]), "+f"((d)[2]), "+f"((d)[3]) \
        : "r"((a)[0]), "r"((a)[1]), "r"((a)[2]), "r"((a)[3]), "r"((b)[0]), "r"((b)[1]))

// ---------------------------------------------------------------------------
// Kernel A: merged prep.  uv fold fully unrolled: same FP order, 64 loads in
// flight instead of 8 (kills the serial-latency chain seen at 7.3us).
// ---------------------------------------------------------------------------
__global__ void prep_kernel(const float* __restrict__ W, const float* __restrict__ attn) {
    int bid = blockIdx.x;
    int k = threadIdx.x;
    if (bid < OUT_CH) {
        g_W16[bid][k] = __float2half_rn(W[bid * IN_DIM_ + k]);
    } else {
        int t = bid - OUT_CH;
        int h = t & 3, side = t >> 2;
        float acc = 0.f;
#pragma unroll
        for (int c = 0; c < C_HID; c++)
            acc += W[(h * C_HID + c) * IN_DIM_ + k] * __ldg(&attn[h * 128 + side * C_HID + c]);
        g_uv[t][k] = acc;
    }
}

// ---------------------------------------------------------------------------
// Kernel C: x -> fp16 + fused attention scores (R12 version)
// ---------------------------------------------------------------------------
__global__ __launch_bounds__(256)
void xprep_kernel(const float* __restrict__ x) {
    const int tid = threadIdx.x, lane = tid & 31, wid = tid >> 5;

    float uvr[8][8];
#pragma unroll
    for (int t = 0; t < 8; t++) {
        float4 a = *(const float4*)&g_uv[t][lane * 8];
        float4 b = *(const float4*)&g_uv[t][lane * 8 + 4];
        uvr[t][0] = a.x; uvr[t][1] = a.y; uvr[t][2] = a.z; uvr[t][3] = a.w;
        uvr[t][4] = b.x; uvr[t][5] = b.y; uvr[t][6] = b.z; uvr[t][7] = b.w;
    }

    const int rowBase = (blockIdx.x * 8 + wid) * 16;
#pragma unroll 2
    for (int r = 0; r < 16; r++) {
        const int row = rowBase + r;
        const float4* xp = (const float4*)(x + (size_t)row * IN_DIM_) + lane * 2;
        float4 v0 = xp[0], v1 = xp[1];
        float xv[8] = {v0.x, v0.y, v0.z, v0.w, v1.x, v1.y, v1.z, v1.w};

        __half hh[8];
#pragma unroll
        for (int i = 0; i < 8; i++) hh[i] = __float2half_rn(xv[i]);
        *(uint4*)(g_x16 + (size_t)row * IN_DIM_ + lane * 8) = *(uint4*)hh;

        float acc[8];
#pragma unroll
        for (int t = 0; t < 8; t++) {
            float s = 0.f;
#pragma unroll
            for (int i = 0; i < 8; i++) s = fmaf(xv[i], uvr[t][i], s);
            acc[t] = s;
        }
#pragma unroll
        for (int t = 0; t < 8; t++) {
#pragma unroll
            for (int off = 16; off > 0; off >>= 1)
                acc[t] += __shfl_xor_sync(0xffffffffu, acc[t], off);
        }
        if (lane == 0) {
            *(float4*)&g_ssrc[row * H_HEADS] = make_float4(acc[0], acc[1], acc[2], acc[3]);
            *(float4*)&g_sdst[row * H_HEADS] = make_float4(acc[4], acc[5], acc[6], acc[7]);
        }
    }
}

// ---------------------------------------------------------------------------
// Kernel D: persistent GEMM (R12 version, 3 CTAs/SM)
// ---------------------------------------------------------------------------
#define GSM_B_BYTES   32768
#define GSM_A_STAGE   8192
#define GSM_TOTAL     (GSM_B_BYTES + 3 * GSM_A_STAGE)

__global__ __launch_bounds__(256, 3)
void gemm_kernel() {
    extern __shared__ char smem[];
    const uint32_t Bq = smem_u32(smem);
    const uint32_t Aq = Bq + GSM_B_BYTES;

    const int tid = threadIdx.x, lane = tid & 31, wid = tid >> 5;
    const int nBase = blockIdx.x * 64;
    const int by = blockIdx.y;
    const int wm = wid >> 1;
    const int wn = wid & 1;

    const int ntiles = (NTILE_M - 1 - by) / NROW + 1;
    const int total = ntiles * 8;

    {
#pragma unroll
        for (int i = 0; i < 8; i++) {
            int cid = i * 256 + tid;
            int n = cid >> 5;
            int c = cid & 31;
            const __half* g = &g_W16[nBase + n][c * 8];
            uint32_t s = Bq + n * 512 + ((c ^ (n & 7)) << 4);
            CP_ASYNC16(s, g);
        }
        CP_COMMIT();
    }

    const int am = tid >> 2, ac = tid & 3;
    const uint32_t as0 = Aq + am * 64 + ((ac ^ ((am >> 1) & 3)) << 4);
    const uint32_t as1 = Aq + (64 + am) * 64 + ((ac ^ (((64 + am) >> 1) & 3)) << 4);
    auto loadQ = [&](int q) {
        int t = q >> 3, kc = q & 7;
        uint32_t st = (uint32_t)(q % 3) * GSM_A_STAGE;
        size_t mb = (size_t)(by + t * NROW) * 128;
        const __half* base = g_x16 + (mb + am) * IN_DIM_ + kc * 32 + ac * 8;
        CP_ASYNC16(as0 + st, base);
        CP_ASYNC16(as1 + st, base + (size_t)64 * IN_DIM_);
        CP_COMMIT();
    };
    loadQ(0);
    loadQ(1);
    CP_WAIT1();
    __syncthreads();

    uint32_t aAddr[2][2];
#pragma unroll
    for (int mi = 0; mi < 2; mi++) {
        int row = wm * 32 + mi * 16 + (lane & 15);
#pragma unroll
        for (int s = 0; s < 2; s++) {
            int c = s * 2 + (lane >> 4);
            aAddr[mi][s] = Aq + row * 64 + ((c ^ ((row >> 1) & 3)) << 4);
        }
    }
    uint32_t bAddr[2][2], bx[2];
#pragma unroll
    for (int bi = 0; bi < 2; bi++) {
        int nrow = wn * 32 + bi * 16 + (lane & 15);
        bx[bi] = (nrow & 4) << 4;
#pragma unroll
        for (int s = 0; s < 2; s++) {
            int t = s * 2 + (lane >> 4);
            bAddr[bi][s] = Bq + nrow * 512 + ((t ^ (nrow & 3)) << 4);
        }
    }

    float acc[2][4][4];
#pragma unroll
    for (int mi = 0; mi < 2; mi++)
#pragma unroll
        for (int ni = 0; ni < 4; ni++)
#pragma unroll
            for (int q = 0; q < 4; q++) acc[mi][ni][q] = 0.f;

    int mBase = by * 128;
    int q = 0;
    uint32_t stOff = 0;
    for (int t = 0; t < ntiles; t++) {
#pragma unroll
        for (int kc = 0; kc < 8; kc++, q++) {
            const uint32_t kcb = kc << 6;
#pragma unroll
            for (int s = 0; s < 2; s++) {
                uint32_t a[2][4];
#pragma unroll
                for (int mi = 0; mi < 2; mi++)
                    LDMX4(a[mi][0], a[mi][1], a[mi][2], a[mi][3], aAddr[mi][s] + stOff);
                uint32_t b[4][2];
#pragma unroll
                for (int bi = 0; bi < 2; bi++) {
                    uint32_t r0, r1, r2, r3;
                    LDMX4(r0, r1, r2, r3, bAddr[bi][s] + (kcb ^ bx[bi]));
                    b[bi * 2 + 0][0] = r0; b[bi * 2 + 0][1] = r2;
                    b[bi * 2 + 1][0] = r1; b[bi * 2 + 1][1] = r3;
                }
#pragma unroll
                for (int mi = 0; mi < 2; mi++)
#pragma unroll
                    for (int ni = 0; ni < 4; ni++)
                        MMA16816(acc[mi][ni], a[mi], b[ni]);
            }
            if (q + 2 < total) loadQ(q + 2); else CP_COMMIT();
            if (q + 1 < total) { CP_WAIT1(); __syncthreads(); }
            stOff = (stOff == 2 * GSM_A_STAGE) ? 0 : stOff + GSM_A_STAGE;
        }

#pragma unroll
        for (int mi = 0; mi < 2; mi++)
#pragma unroll
            for (int ni = 0; ni < 4; ni++) {
                int row0 = mBase + wm * 32 + mi * 16 + (lane >> 2);
                int col  = nBase + wn * 32 + ni * 8 + (lane & 3) * 2;
                __half2 v0 = __floats2half2_rn(acc[mi][ni][0], acc[mi][ni][1]);
                __half2 v1 = __floats2half2_rn(acc[mi][ni][2], acc[mi][ni][3]);
                *(__half2*)&g_h16[(size_t)row0 * OUT_CH + col] = v0;
                *(__half2*)&g_h16[(size_t)(row0 + 8) * OUT_CH + col] = v1;
#pragma unroll
                for (int qq = 0; qq < 4; qq++) acc[mi][ni][qq] = 0.f;
            }
        mBase += NROW * 128;
    }
}

// ---------------------------------------------------------------------------
// Kernel E: softmax + aggregation.
//  vs R12: gathers use __ldcg (L2-only, h rows have no L1 reuse) and the
//  index/weight hoists are split into two 8-neighbor halves (regs 38 -> ~31).
//  FP math order identical to R12.
// ---------------------------------------------------------------------------
__global__ __launch_bounds__(256)
void agg_kernel(const int* __restrict__ nidx, float* __restrict__ out) {
    __shared__ float salpha[8][H_HEADS][K_NB];
    int gw   = (blockIdx.x * blockDim.x + threadIdx.x) >> 5;
    int lane = threadIdx.x & 31;
    int wid  = (threadIdx.x >> 5);
    if (gw >= M_ROWS) return;

    const int b = gw / N_NODES;
    const int k = lane & 15;
    const int j = __ldg(&nidx[gw * K_NB + k]);
    const int jr = b * N_NODES + j;
    const float scale = 0.125f;

    float4 ssv = *(const float4*)&g_ssrc[gw * H_HEADS];
    float4 sdv = *(const float4*)&g_sdst[jr * H_HEADS];
    float e[H_HEADS] = {(ssv.x + sdv.x) * scale, (ssv.y + sdv.y) * scale,
                        (ssv.z + sdv.z) * scale, (ssv.w + sdv.w) * scale};
    float alpha[H_HEADS];
#pragma unroll
    for (int hh = 0; hh < H_HEADS; hh++) {
        float m = e[hh];
#pragma unroll
        for (int off = 8; off > 0; off >>= 1)
            m = fmaxf(m, __shfl_xor_sync(0xffffffffu, m, off));
        float ex = __expf(e[hh] - m);
        float s = ex;
#pragma unroll
        for (int off = 8; off > 0; off >>= 1)
            s += __shfl_xor_sync(0xffffffffu, s, off);
        alpha[hh] = ex / s;
    }
    if (lane < 16) {
#pragma unroll
        for (int hh = 0; hh < H_HEADS; hh++)
            salpha[wid][hh][lane] = alpha[hh];
    }
    __syncwarp();

    const int myhead = lane >> 3;
    const __half* hbase = g_h16 + ((size_t)b * N_NODES) * OUT_CH + lane * 8;
    const int4* np = (const int4*)&nidx[gw * K_NB];

    __half2 accA[4], accB[4];
#pragma unroll
    for (int i = 0; i < 4; i++) {
        accA[i] = __float2half2_rn(0.f);
        accB[i] = __float2half2_rn(0.f);
    }

    // ---- half 1: neighbors 0..7
    {
        int ja[8];
        *(int4*)&ja[0] = __ldg(&np[0]);
        *(int4*)&ja[4] = __ldg(&np[1]);
        __half2 wh[8];
        {
            float wt[8];
            *(float4*)&wt[0] = *(const float4*)&salpha[wid][myhead][0];
            *(float4*)&wt[4] = *(const float4*)&salpha[wid][myhead][4];
#pragma unroll
            for (int kk = 0; kk < 8; kk++) wh[kk] = __float2half2_rn(wt[kk]);
        }
#pragma unroll
        for (int kk = 0; kk < 8; kk++) {
            int4 vi = __ldcg((const int4*)(hbase + (size_t)ja[kk] * OUT_CH));
            const __half2* hv = (const __half2*)&vi;
#pragma unroll
            for (int qq = 0; qq < 4; qq++)
                accA[qq] = __hfma2(wh[kk], hv[qq], accA[qq]);
        }
    }
    // ---- half 2: neighbors 8..15
    {
        int ja[8];
        *(int4*)&ja[0] = __ldg(&np[2]);
        *(int4*)&ja[4] = __ldg(&np[3]);
        __half2 wh[8];
        {
            float wt[8];
            *(float4*)&wt[0] = *(const float4*)&salpha[wid][myhead][8];
            *(float4*)&wt[4] = *(const float4*)&salpha[wid][myhead][12];
#pragma unroll
            for (int kk = 0; kk < 8; kk++) wh[kk] = __float2half2_rn(wt[kk]);
        }
#pragma unroll
        for (int kk = 0; kk < 8; kk++) {
            int4 vi = __ldcg((const int4*)(hbase + (size_t)ja[kk] * OUT_CH));
            const __half2* hv = (const __half2*)&vi;
#pragma unroll
            for (int qq = 0; qq < 4; qq++)
                accB[qq] = __hfma2(wh[kk], hv[qq], accB[qq]);
        }
    }

    float acc[8];
#pragma unroll
    for (int qq = 0; qq < 4; qq++) {
        float2 fa = __half22float2(accA[qq]);
        float2 fb = __half22float2(accB[qq]);
        acc[2 * qq + 0] = fa.x + fb.x;
        acc[2 * qq + 1] = fa.y + fb.y;
    }

#pragma unroll
    for (int i = 0; i < 8; i++) {
        acc[i] += __shfl_xor_sync(0xffffffffu, acc[i], 8);
        acc[i] += __shfl_xor_sync(0xffffffffu, acc[i], 16);
    }

    if (lane < 8) {
        float4 o0 = make_float4(acc[0] * 0.25f, acc[1] * 0.25f, acc[2] * 0.25f, acc[3] * 0.25f);
        float4 o1 = make_float4(acc[4] * 0.25f, acc[5] * 0.25f, acc[6] * 0.25f, acc[7] * 0.25f);
        float* op = out + (size_t)gw * C_HID + lane * 8;
        *(float4*)op = o0;
        *(float4*)(op + 4) = o1;
    }
}

// ---------------------------------------------------------------------------
extern "C" void kernel_launch(void* const* d_in, const int* in_sizes, int n_in,
                              void* d_out, int out_size) {
    const float* x    = (const float*)d_in[0];
    const int*   nidx = (const int*)d_in[1];
    const float* W    = (const float*)d_in[2];
    const float* attn = (const float*)d_in[3];
    float* out = (float*)d_out;

    cudaFuncSetAttribute(gemm_kernel, cudaFuncAttributeMaxDynamicSharedMemorySize, GSM_TOTAL);

    prep_kernel<<<OUT_CH + 8, 256>>>(W, attn);
    xprep_kernel<<<M_ROWS / 128, 256>>>(x);
    gemm_kernel<<<dim3(4, NROW), 256, GSM_TOTAL>>>();
    agg_kernel<<<M_ROWS / 8, 256>>>(nidx, out);
}